// round 15
// baseline (speedup 1.0000x reference)
#include <cuda_runtime.h>

#define N 256
#define T 512
#define GRID 128         // 2 anchors per block
#define PROW 257         // padded partials row stride (float2 units)

// Scratch (allocations forbidden)
__device__ float2   g_part[GRID];
__device__ unsigned g_count = 0;

// Dynamic smem: s_p float2[32*PROW] | dn0[256] | dn1[256] | lab[256]
//               | wmax float2[8] | ws float2[8]
#define SMEM_BYTES (32 * PROW * 8 + 3 * N * 4 + 8 * 8 + 8 * 8)

extern __shared__ char smem_raw[];

__global__ void __launch_bounds__(T)
fused_kernel(const int* __restrict__ raw,
             const float* __restrict__ emb,
             float* __restrict__ out) {
    float2* s_p    = (float2*)smem_raw;                 // [lane][row]
    float*  s_dn0  = (float*)(smem_raw + 32 * PROW * 8); // 16B-aligned
    float*  s_dn1  = s_dn0 + N;
    int*    s_lab  = (int*)(s_dn1 + N);
    float2* s_wmax = (float2*)(s_lab + N);
    float2* s_ws   = s_wmax + 8;

    const int t    = threadIdx.x;
    const int lane = t & 31;
    const int w    = t >> 5;                   // 16 warps
    const int b    = blockIdx.x;
    const int i0   = 2 * b, i1 = 2 * b + 1;

    // --- Anchor rows: coalesced LDG.128, warp-uniform address ---
    const float4* e4 = reinterpret_cast<const float4*>(emb);
    const float4 a0 = __ldg(e4 + i0 * 32 + lane);
    const float4 a1 = __ldg(e4 + i1 * 32 + lane);

    // --- Warp-local label decode (warps 0-7; no block barrier).
    //     Probe odd words within the FIRST 256 int32 words (in-bounds both
    //     layouts): int64 -> zero high-words; int32 -> random labels 0..15,
    //     P(32 zeros) = 16^-32 ~ 0. Deterministic either way.
    if (w < 8) {
        const int k = t;                       // 0..255
        int probe = raw[2 * (t & 127) + 1];
        int is64 = !__any_sync(0xffffffffu, probe != 0);
        s_lab[k] = is64 ? raw[2 * k] : raw[k];
    }

    // --- Dot phase (R7): warp w owns rows w+16j; per-lane partials over 4 cols ---
    // d^2 = sum (a_i - a_k)^2
#pragma unroll
    for (int j = 0; j < 16; j++) {
        const int row = w + 16 * j;
        float4 x = __ldg(e4 + row * 32 + lane);      // coalesced 512B per warp
        float dx = x.x - a0.x, dy = x.y - a0.y, dz = x.z - a0.z, dw = x.w - a0.w;
        float s0 = dx * dx + dy * dy + dz * dz + dw * dw;
        dx = x.x - a1.x; dy = x.y - a1.y; dz = x.z - a1.z; dw = x.w - a1.w;
        float s1 = dx * dx + dy * dy + dz * dz + dw * dw;
        s_p[lane * PROW + row] = make_float2(s0, s1);   // conflict-free STS.64
    }
    __syncthreads();                                 // bar A: partials + labels

    // --- Threads 0..255: transpose-reduce 32 partials for row k (R7) ---
    float d0 = 0.f, d1 = 0.f;
    unsigned bp0 = 0, bp1 = 0;
    if (t < N) {
        const int k = t;
        float ax = 0.f, ay = 0.f, bx = 0.f, by = 0.f;
        float cx = 0.f, cy = 0.f, ex = 0.f, ey = 0.f;
#pragma unroll
        for (int l = 0; l < 32; l += 4) {            // conflict-free LDS.64
            float2 v0 = s_p[(l + 0) * PROW + k];
            float2 v1 = s_p[(l + 1) * PROW + k];
            float2 v2 = s_p[(l + 2) * PROW + k];
            float2 v3 = s_p[(l + 3) * PROW + k];
            ax += v0.x; ay += v0.y;
            bx += v1.x; by += v1.y;
            cx += v2.x; cy += v2.y;
            ex += v3.x; ey += v3.y;
        }
        const float s0 = (ax + bx) + (cx + ex);      // fixed combine order
        const float s1 = (ay + by) + (cy + ey);
        // clip(.,0) then clip(.,EPS) == max(.,EPS)
        d0 = sqrtf(fmaxf(s0, 1e-4f));
        d1 = sqrtf(fmaxf(s1, 1e-4f));

        const int lk = s_lab[k], l0 = s_lab[i0], l1 = s_lab[i1];
        const bool neg0 = (lk != l0) || (k == i0);
        const bool neg1 = (lk != l1) || (k == i1);
        const bool pos0 = (lk == l0) && (k != i0);
        const bool pos1 = (lk == l1) && (k != i1);

        // masked distances (d >= 0.01 > -1, -1 never passes "> d")
        const float dn0 = neg0 ? d0 : -1.f;
        const float dn1 = neg1 ? d1 : -1.f;
        s_dn0[k] = dn0;
        s_dn1[k] = dn1;

        float mA = dn0, mB = dn1;
#pragma unroll
        for (int off = 16; off > 0; off >>= 1) {     // fixed-order butterfly
            mA = fmaxf(mA, __shfl_xor_sync(0xffffffffu, mA, off));
            mB = fmaxf(mB, __shfl_xor_sync(0xffffffffu, mB, off));
        }
        bp0 = __ballot_sync(0xffffffffu, pos0);
        bp1 = __ballot_sync(0xffffffffu, pos1);
        if (lane == 0) s_wmax[w] = make_float2(mA, mB);
    }
    __syncthreads();                                 // bar B: dn + wmax ready

    // --- Warps 0-7: scan own positive lanes, both anchors (R14 tail) ---
    if (w < 8) {
        float2 wm0 = s_wmax[0], wm1 = s_wmax[1], wm2 = s_wmax[2], wm3 = s_wmax[3];
        float2 wm4 = s_wmax[4], wm5 = s_wmax[5], wm6 = s_wmax[6], wm7 = s_wmax[7];
        const float max0 = fmaxf(fmaxf(fmaxf(wm0.x, wm1.x), fmaxf(wm2.x, wm3.x)),
                                 fmaxf(fmaxf(wm4.x, wm5.x), fmaxf(wm6.x, wm7.x)));
        const float max1 = fmaxf(fmaxf(fmaxf(wm0.y, wm1.y), fmaxf(wm2.y, wm3.y)),
                                 fmaxf(fmaxf(wm4.y, wm5.y), fmaxf(wm6.y, wm7.y)));
        // hoisted scan operands: lane covers 8 of 256 dn values per anchor
        const float4* p0 = reinterpret_cast<const float4*>(s_dn0);
        const float4* p1 = reinterpret_cast<const float4*>(s_dn1);
        const float4 u0 = p0[lane], v0 = p0[lane + 32];   // conflict-free LDS.128
        const float4 u1 = p1[lane], v1 = p1[lane + 32];

        float wsum = 0.f;
        unsigned rem = bp0;                               // warp-uniform
        while (rem) {                                     // anchor-0 entries, ascending
            const int src = __ffs(rem) - 1;
            rem &= rem - 1u;
            const float dv = __shfl_sync(0xffffffffu, d0, src);
            float m = 3.402823466e+38f;
            if (u0.x > dv) m = fminf(m, u0.x);
            if (u0.y > dv) m = fminf(m, u0.y);
            if (u0.z > dv) m = fminf(m, u0.z);
            if (u0.w > dv) m = fminf(m, u0.w);
            if (v0.x > dv) m = fminf(m, v0.x);
            if (v0.y > dv) m = fminf(m, v0.y);
            if (v0.z > dv) m = fminf(m, v0.z);
            if (v0.w > dv) m = fminf(m, v0.w);
#pragma unroll
            for (int off = 16; off > 0; off >>= 1)
                m = fminf(m, __shfl_xor_sync(0xffffffffu, m, off));
            // mask_final <=> exists d_ij > d_ik <=> maxd > d_ik
            const float semi = (max0 > dv) ? (dv - m) : (dv - max0);
            wsum += fmaxf(0.f, semi + 1.0f);              // uniform across lanes
        }
        rem = bp1;
        while (rem) {                                     // anchor-1 entries, ascending
            const int src = __ffs(rem) - 1;
            rem &= rem - 1u;
            const float dv = __shfl_sync(0xffffffffu, d1, src);
            float m = 3.402823466e+38f;
            if (u1.x > dv) m = fminf(m, u1.x);
            if (u1.y > dv) m = fminf(m, u1.y);
            if (u1.z > dv) m = fminf(m, u1.z);
            if (u1.w > dv) m = fminf(m, u1.w);
            if (v1.x > dv) m = fminf(m, v1.x);
            if (v1.y > dv) m = fminf(m, v1.y);
            if (v1.z > dv) m = fminf(m, v1.z);
            if (v1.w > dv) m = fminf(m, v1.w);
#pragma unroll
            for (int off = 16; off > 0; off >>= 1)
                m = fminf(m, __shfl_xor_sync(0xffffffffu, m, off));
            const float semi = (max1 > dv) ? (dv - m) : (dv - max1);
            wsum += fmaxf(0.f, semi + 1.0f);
        }
        if (lane == 0)
            s_ws[w] = make_float2(wsum, (float)(__popc(bp0) + __popc(bp1)));
    }
    __syncthreads();                                      // bar C: warp sums ready

    // --- Warp 0: combine 8 warp sums + cross-block handoff ---
    if (t < 32) {
        float2 r = (lane < 8) ? s_ws[lane] : make_float2(0.f, 0.f);
#pragma unroll
        for (int off = 4; off > 0; off >>= 1) {           // fixed-order reduce over 8
            r.x += __shfl_xor_sync(0xffffffffu, r.x, off);
            r.y += __shfl_xor_sync(0xffffffffu, r.y, off);
        }

        unsigned rank = 0;
        if (lane == 0) {
            g_part[b] = make_float2(r.x, r.y);
            // acq_rel completion count: release publishes g_part[b]; the last
            // block's acquire orders its g_part reads below.
            asm volatile("atom.add.acq_rel.gpu.u32 %0, [%1], 1;"
                         : "=r"(rank) : "l"(&g_count) : "memory");
        }
        rank = __shfl_sync(0xffffffffu, rank, 0);

        // --- Last block: deterministic final reduction over 128 partials ---
        if (rank == GRID - 1) {
            float sx = 0.f, sy = 0.f;
#pragma unroll
            for (int q = 0; q < 4; q++) {
                const float2* gp = (const float2*)g_part + lane + q * 32;
                float2 vv;
                asm volatile("ld.global.cg.v2.f32 {%0,%1}, [%2];"
                             : "=f"(vv.x), "=f"(vv.y) : "l"(gp));
                sx += vv.x; sy += vv.y;
            }
#pragma unroll
            for (int off = 16; off > 0; off >>= 1) {
                sx += __shfl_xor_sync(0xffffffffu, sx, off);
                sy += __shfl_xor_sync(0xffffffffu, sy, off);
            }
            if (lane == 0) {
                out[0] = sx / sy;
                g_count = 0;                              // reset for replay
            }
        }
    }
}

extern "C" void kernel_launch(void* const* d_in, const int* in_sizes, int n_in,
                              void* d_out, int out_size) {
    const float* emb = (const float*)d_in[0];
    const int*   lab = (const int*)d_in[1];  // int32 view; kernel autodetects int64
    (void)in_sizes; (void)n_in; (void)out_size;

    cudaFuncSetAttribute(fused_kernel,
                         cudaFuncAttributeMaxDynamicSharedMemorySize, SMEM_BYTES);
    fused_kernel<<<GRID, T, SMEM_BYTES>>>(lab, emb, (float*)d_out);
}

// round 16
// speedup vs baseline: 1.2081x; 1.2081x over previous
#include <cuda_runtime.h>

#define N 256
#define T 512
#define GRID 256         // 1 anchor per block, 2 blocks co-resident per SM
#define PROW 257         // padded partials row stride (floats)

// Scratch (allocations forbidden)
__device__ float2   g_part[GRID];
__device__ unsigned g_count = 0;

__global__ void __launch_bounds__(T, 2)
fused_kernel(const int* __restrict__ raw,
             const float* __restrict__ emb,
             float* __restrict__ out) {
    __shared__ float s_p[32 * PROW];           // partials[lane][row], 32.9KB
    __shared__ float s_dn[N];                  // masked distances
    __shared__ int   s_lab[N];
    __shared__ float s_wmax[8];
    __shared__ int   s_cnt[8];
    __shared__ float s_ed[N];                  // compacted positive distances
    __shared__ float s_val[N];

    const int t    = threadIdx.x;
    const int lane = t & 31;
    const int w    = t >> 5;                   // 16 warps
    const int i    = blockIdx.x;               // anchor index

    // --- Anchor row first: coalesced LDG.128, same addr across warps ---
    const float4* e4 = reinterpret_cast<const float4*>(emb);
    const float4 a = __ldg(e4 + i * 32 + lane);

    // --- Warp-local label decode (warps 0-7; no block barrier needed).
    //     Probe odd words within the FIRST 256 int32 words only (in-bounds
    //     for both layouts): int64 -> zero high-words; int32 -> random 0..15,
    //     P(32 zeros) = 16^-32 ~ 0. Deterministic either way.
    if (w < 8) {
        const int k = t;                       // 0..255
        int probe = raw[2 * (t & 127) + 1];
        int is64 = !__any_sync(0xffffffffu, probe != 0);
        s_lab[k] = is64 ? raw[2 * k] : raw[k];
    }

    // --- Dot phase: warp w owns rows w+16j ---
    // d^2 = sum (a_i - a_k)^2 ; per-lane partial over 4 columns
#pragma unroll
    for (int j = 0; j < 16; j++) {
        const int row = w + 16 * j;
        float4 x = __ldg(e4 + row * 32 + lane);      // coalesced 512B per warp
        float dx = x.x - a.x, dy = x.y - a.y, dz = x.z - a.z, dw = x.w - a.w;
        s_p[lane * PROW + row] = dx * dx + dy * dy + dz * dz + dw * dw;
    }
    __syncthreads();                                 // bar A: partials + labels

    // --- Threads 0..255: transpose-reduce 32 partials for row k ---
    float d = 0.f;
    bool pos = false;
    unsigned bp = 0;
    if (t < N) {
        const int k = t;
        float ax = 0.f, bx = 0.f, cx = 0.f, dx4 = 0.f;
#pragma unroll
        for (int l = 0; l < 32; l += 4) {            // conflict-free LDS.32
            ax  += s_p[(l + 0) * PROW + k];
            bx  += s_p[(l + 1) * PROW + k];
            cx  += s_p[(l + 2) * PROW + k];
            dx4 += s_p[(l + 3) * PROW + k];
        }
        const float s2 = (ax + bx) + (cx + dx4);     // fixed combine order
        // clip(.,0) then clip(.,EPS) == max(.,EPS)
        d = sqrtf(fmaxf(s2, 1e-4f));

        const int  lk  = s_lab[k], li = s_lab[i];
        const bool neg = (lk != li) || (k == i);     // j-set membership
        pos = (lk == li) && (k != i);

        // masked distance (d >= 0.01 > -1, -1 never passes "> d")
        const float dn = neg ? d : -1.f;
        s_dn[k] = dn;

        float mx = dn;
#pragma unroll
        for (int off = 16; off > 0; off >>= 1)       // fixed-order butterfly
            mx = fmaxf(mx, __shfl_xor_sync(0xffffffffu, mx, off));
        bp = __ballot_sync(0xffffffffu, pos);
        if (lane == 0) {
            s_wmax[w] = mx;
            s_cnt[w]  = __popc(bp);
        }
    }
    __syncthreads();                                 // bar B

    // --- Deterministic compaction slots + block maxd + count (all threads) ---
    int C = 0, pfx = 0;
    float maxd = -1.f;
#pragma unroll
    for (int q = 0; q < 8; q++) {
        int c = s_cnt[q];
        if (q < w) pfx += c;
        C += c;
        maxd = fmaxf(maxd, s_wmax[q]);
    }
    if (pos) {
        unsigned lt = (1u << lane) - 1u;
        s_ed[pfx + __popc(bp & lt)] = d;
    }
    __syncthreads();                                 // bar C

    // --- Warp-cooperative successor-min scan; C ~ 15 => one round ---
    const float4* p4 = reinterpret_cast<const float4*>(s_dn);
    for (int e = w; e < C; e += 16) {
        const float dv = s_ed[e];                    // broadcast
        float4 u = p4[lane], v = p4[lane + 32];      // conflict-free LDS.128
        float m = 3.402823466e+38f;
        if (u.x > dv) m = fminf(m, u.x);
        if (u.y > dv) m = fminf(m, u.y);
        if (u.z > dv) m = fminf(m, u.z);
        if (u.w > dv) m = fminf(m, u.w);
        if (v.x > dv) m = fminf(m, v.x);
        if (v.y > dv) m = fminf(m, v.y);
        if (v.z > dv) m = fminf(m, v.z);
        if (v.w > dv) m = fminf(m, v.w);
#pragma unroll
        for (int off = 16; off > 0; off >>= 1)
            m = fminf(m, __shfl_xor_sync(0xffffffffu, m, off));
        if (lane == 0) {
            // mask_final <=> exists d_ij > d_ik <=> maxd > d_ik
            const float semi = (maxd > dv) ? (dv - m) : (dv - maxd);
            s_val[e] = fmaxf(0.f, semi + 1.0f);
        }
    }
    __syncthreads();                                 // bar D

    // --- Warp 0: fixed-order block sum + cross-block handoff ---
    if (t < 32) {
        float sv = 0.f;
        for (int e = lane; e < C; e += 32) sv += s_val[e];
#pragma unroll
        for (int off = 16; off > 0; off >>= 1)
            sv += __shfl_xor_sync(0xffffffffu, sv, off);

        unsigned rank = 0;
        if (lane == 0) {
            g_part[i] = make_float2(sv, (float)C);
            // acq_rel completion count: release publishes g_part[i]; the last
            // block's acquire orders its g_part reads below. (Replaces
            // __threadfence + relaxed atomic — one fewer MEMBAR per block.)
            asm volatile("atom.add.acq_rel.gpu.u32 %0, [%1], 1;"
                         : "=r"(rank) : "l"(&g_count) : "memory");
        }
        rank = __shfl_sync(0xffffffffu, rank, 0);

        // --- Last block: deterministic final reduction over 256 partials ---
        if (rank == GRID - 1) {
            float sx = 0.f, sy = 0.f;
#pragma unroll
            for (int q = 0; q < 8; q++) {
                const float2* gp = (const float2*)g_part + lane + q * 32;
                float2 vv;
                asm volatile("ld.global.cg.v2.f32 {%0,%1}, [%2];"
                             : "=f"(vv.x), "=f"(vv.y) : "l"(gp));
                sx += vv.x; sy += vv.y;
            }
#pragma unroll
            for (int off = 16; off > 0; off >>= 1) {
                sx += __shfl_xor_sync(0xffffffffu, sx, off);
                sy += __shfl_xor_sync(0xffffffffu, sy, off);
            }
            if (lane == 0) {
                out[0] = sx / sy;
                g_count = 0;                         // reset for replay
            }
        }
    }
}

extern "C" void kernel_launch(void* const* d_in, const int* in_sizes, int n_in,
                              void* d_out, int out_size) {
    const float* emb = (const float*)d_in[0];
    const int*   lab = (const int*)d_in[1];  // int32 view; kernel autodetects int64
    (void)in_sizes; (void)n_in; (void)out_size;

    fused_kernel<<<GRID, T>>>(lab, emb, (float*)d_out);
}